// round 6
// baseline (speedup 1.0000x reference)
#include <cuda_runtime.h>
#include <cstdint>

#define VOCAB   50257
#define BATCH   512
#define SEQ     1024

// ---------------- fill kernel: flat zero of the whole output ----------------
// 512*50257 floats = exactly 6,432,896 float4 (16B), base 256B-aligned.
#define TOTAL_VEC   ((BATCH * (size_t)VOCAB) / 4)
#define FILL_CTAS   2368           // 16 * 148
#define FILL_THR    256

__global__ void __launch_bounds__(FILL_THR)
fill_kernel(float4* __restrict__ out)
{
    const size_t stride = (size_t)FILL_CTAS * FILL_THR;
    size_t i = (size_t)blockIdx.x * FILL_THR + threadIdx.x;
    const float4 z4 = make_float4(0.f, 0.f, 0.f, 0.f);
    // default eviction: keep the freshly-zeroed lines in L2 so the scatter
    // kernel's REDs hit L2 instead of doing DRAM sector RMWs.
    #pragma unroll 4
    for (; i < TOTAL_VEC; i += stride)
        out[i] = z4;
}

// ------------- scatter kernel: n-reduction + global RED adds ---------------
// No histogram: duplicates accumulate via atomicAdd (RED, no return value).
#define STHREADS 512

__global__ void __launch_bounds__(STHREADS, 8)
scatter_kernel(const void* __restrict__ xraw,
               const float* __restrict__ idf,
               float* __restrict__ out)
{
    const int b    = blockIdx.x;
    const int tid  = threadIdx.x;
    const int lane = tid & 31;
    const int wid  = tid >> 5;
    __shared__ float sh_part[STHREADS / 32];
    __shared__ float sh_n;

    // dtype detection, warp-local, no barrier: if tokens are int32, a u64 read
    // packs two tokens and is >= VOCAB unless the odd token is 0; probability
    // all 32 probes are small is (1/50257)^32 ~ 0. Uniform across warps.
    const unsigned long long probe = ((const unsigned long long*)xraw)[lane];
    const int is64 = (__ballot_sync(0xffffffffu, probe >= (unsigned long long)VOCAB) == 0);

    const size_t base = (size_t)b * SEQ;
    int tok0, tok1;
    if (is64) {
        tok0 = (int)((const long long*)xraw)[base + tid];
        tok1 = (int)((const long long*)xraw)[base + tid + STHREADS];
    } else {
        tok0 = ((const int*)xraw)[base + tid];
        tok1 = ((const int*)xraw)[base + tid + STHREADS];
    }
    const float idf0 = __ldg(&idf[tok0]);
    const float idf1 = __ldg(&idf[tok1]);

    // n = sum over the row of idf[tok]
    float w = idf0 + idf1;
    #pragma unroll
    for (int o = 16; o > 0; o >>= 1)
        w += __shfl_down_sync(0xffffffffu, w, o);
    if (lane == 0) sh_part[wid] = w;
    __syncthreads();
    if (wid == 0) {
        float v = (lane < STHREADS / 32) ? sh_part[lane] : 0.0f;
        #pragma unroll
        for (int o = 8; o > 0; o >>= 1)
            v += __shfl_down_sync(0xffffffffu, v, o);
        if (lane == 0) sh_n = v;
    }
    __syncthreads();

    // scatter-accumulate: duplicates sum to count*idf*inv_n automatically.
    // atomicAdd with unused result -> REDG (fire-and-forget), L2-hit after fill.
    const float inv_n = 1.0f / sh_n;
    float* __restrict__ orow = out + (size_t)b * VOCAB;
    atomicAdd(&orow[tok0], idf0 * inv_n);
    atomicAdd(&orow[tok1], idf1 * inv_n);
}

extern "C" void kernel_launch(void* const* d_in, const int* in_sizes, int n_in,
                              void* d_out, int out_size)
{
    const void*  x   = d_in[0];
    const float* idf = (const float*)d_in[1];
    float*       out = (float*)d_out;

    fill_kernel<<<FILL_CTAS, FILL_THR>>>((float4*)out);
    scatter_kernel<<<BATCH, STHREADS>>>(x, idf, out);
}

// round 7
// speedup vs baseline: 1.0643x; 1.0643x over previous
#include <cuda_runtime.h>
#include <cstdint>

#define VOCAB   50257
#define BATCH   512
#define SEQ     1024

// ---------------- fill kernel: flat zero of the whole output ----------------
// 512*50257 floats = exactly 6,432,896 float4 (16B), base 256B-aligned.
// R5-verified config: __stcs + 1184 CTAs -> ~9.5us.
#define TOTAL_VEC   ((BATCH * (size_t)VOCAB) / 4)
#define FILL_CTAS   1184           // 8 * 148
#define FILL_THR    256

__global__ void __launch_bounds__(FILL_THR)
fill_kernel(float4* __restrict__ out)
{
    // Let the dependent (scatter) grid launch immediately; its prologue
    // doesn't touch `out` and overlaps with this fill.
    asm volatile("griddepcontrol.launch_dependents;" ::: "memory");

    const size_t stride = (size_t)FILL_CTAS * FILL_THR;
    size_t i = (size_t)blockIdx.x * FILL_THR + threadIdx.x;
    const float4 z4 = make_float4(0.f, 0.f, 0.f, 0.f);
    #pragma unroll 4
    for (; i < TOTAL_VEC; i += stride)
        __stcs(&out[i], z4);
}

// ------------- scatter kernel: n-reduction + global RED adds ---------------
// No histogram: duplicate tokens accumulate via fire-and-forget atomicAdd.
#define STHREADS 512

__global__ void __launch_bounds__(STHREADS, 8)
scatter_kernel(const void* __restrict__ xraw,
               const float* __restrict__ idf,
               float* __restrict__ out)
{
    const int b    = blockIdx.x;
    const int tid  = threadIdx.x;
    const int lane = tid & 31;
    const int wid  = tid >> 5;
    __shared__ float sh_part[STHREADS / 32];
    __shared__ float sh_n;

    // dtype detection, warp-local, no barrier: if tokens are int32, a u64 read
    // packs two tokens and is >= VOCAB unless the odd token is 0; probability
    // all 32 probes are small is (1/50257)^32 ~ 0. Uniform across warps.
    const unsigned long long probe = ((const unsigned long long*)xraw)[lane];
    const int is64 = (__ballot_sync(0xffffffffu, probe >= (unsigned long long)VOCAB) == 0);

    const size_t base = (size_t)b * SEQ;
    int tok0, tok1;
    if (is64) {
        tok0 = (int)((const long long*)xraw)[base + tid];
        tok1 = (int)((const long long*)xraw)[base + tid + STHREADS];
    } else {
        tok0 = ((const int*)xraw)[base + tid];
        tok1 = ((const int*)xraw)[base + tid + STHREADS];
    }
    const float idf0 = __ldg(&idf[tok0]);
    const float idf1 = __ldg(&idf[tok1]);

    // n = sum over the row of idf[tok]
    float w = idf0 + idf1;
    #pragma unroll
    for (int o = 16; o > 0; o >>= 1)
        w += __shfl_down_sync(0xffffffffu, w, o);
    if (lane == 0) sh_part[wid] = w;
    __syncthreads();
    if (wid == 0) {
        float v = (lane < STHREADS / 32) ? sh_part[lane] : 0.0f;
        #pragma unroll
        for (int o = 8; o > 0; o >>= 1)
            v += __shfl_down_sync(0xffffffffu, v, o);
        if (lane == 0) sh_n = v;
    }
    __syncthreads();
    const float inv_n = 1.0f / sh_n;

    // Wait for the fill grid's memory to be visible, then scatter-accumulate.
    asm volatile("griddepcontrol.wait;" ::: "memory");

    float* __restrict__ orow = out + (size_t)b * VOCAB;
    atomicAdd(&orow[tok0], idf0 * inv_n);
    atomicAdd(&orow[tok1], idf1 * inv_n);
}

extern "C" void kernel_launch(void* const* d_in, const int* in_sizes, int n_in,
                              void* d_out, int out_size)
{
    const void*  x   = d_in[0];
    const float* idf = (const float*)d_in[1];
    float*       out = (float*)d_out;

    fill_kernel<<<FILL_CTAS, FILL_THR>>>((float4*)out);

    // Scatter launched with programmatic stream serialization: it may begin
    // as soon as fill's blocks have all started (launch_dependents); its
    // griddepcontrol.wait supplies the real ordering before the atomics.
    cudaLaunchConfig_t cfg = {};
    cfg.gridDim  = dim3(BATCH);
    cfg.blockDim = dim3(STHREADS);
    cfg.dynamicSmemBytes = 0;
    cfg.stream = 0;
    cudaLaunchAttribute attr[1];
    attr[0].id = cudaLaunchAttributeProgrammaticStreamSerialization;
    attr[0].val.programmaticStreamSerializationAllowed = 1;
    cfg.attrs = attr;
    cfg.numAttrs = 1;
    cudaLaunchKernelEx(&cfg, scatter_kernel, (const void*)x, idf, out);
}

// round 8
// speedup vs baseline: 1.1620x; 1.0918x over previous
#include <cuda_runtime.h>
#include <cstdint>

#define VOCAB   50257
#define BATCH   512
#define SEQ     1024
#define THREADS 512

__global__ void __launch_bounds__(THREADS, 4)
tfidf_kernel(const void* __restrict__ xraw,
             const float* __restrict__ idf,
             float* __restrict__ out)
{
    const int b    = blockIdx.x;
    const int tid  = threadIdx.x;
    const int lane = tid & 31;
    const int wid  = tid >> 5;
    __shared__ float sh_part[THREADS / 32];
    __shared__ float sh_n;

    // dtype detection, warp-local, no barrier: if tokens are int32, a u64 read
    // packs two tokens and is >= VOCAB unless the odd token is 0; probability
    // all 32 probes are small is (1/50257)^32 ~ 0. Uniform across warps.
    const unsigned long long probe = ((const unsigned long long*)xraw)[lane];
    const int is64 = (__ballot_sync(0xffffffffu, probe >= (unsigned long long)VOCAB) == 0);

    // ---- token loads + idf gathers (LDGs in flight before the fill) ----
    const size_t base = (size_t)b * SEQ;
    int tok0, tok1;
    if (is64) {
        tok0 = (int)((const long long*)xraw)[base + tid];
        tok1 = (int)((const long long*)xraw)[base + tid + THREADS];
    } else {
        tok0 = ((const int*)xraw)[base + tid];
        tok1 = ((const int*)xraw)[base + tid + THREADS];
    }
    const float idf0 = __ldg(&idf[tok0]);
    const float idf1 = __ldg(&idf[tok1]);

    // ---- stream-zero own row (same aggregate pattern as the 9.5us fill) ----
    float* __restrict__ orow = out + (size_t)b * VOCAB;
    {
        const int pre   = (int)(((16u - ((unsigned)(uintptr_t)orow & 15u)) & 15u) >> 2);
        float4* __restrict__ ov = (float4*)(orow + pre);
        const int nvec  = (VOCAB - pre) >> 2;
        const int tail0 = pre + (nvec << 2);

        if (tid < pre) orow[tid] = 0.0f;                        // <=3 scalars
        const float4 z4 = make_float4(0.f, 0.f, 0.f, 0.f);
        #pragma unroll 4
        for (int i = tid; i < nvec; i += THREADS) __stcs(&ov[i], z4);
        if (tid < VOCAB - tail0) orow[tail0 + tid] = 0.0f;      // <=3 scalars
    }

    // ---- n = sum idf[tok] over the row (overlaps with store drain) ----
    float w = idf0 + idf1;
    #pragma unroll
    for (int o = 16; o > 0; o >>= 1)
        w += __shfl_down_sync(0xffffffffu, w, o);
    if (lane == 0) sh_part[wid] = w;
    __syncthreads();    // also orders our zero STGs before the REDs below
    if (wid == 0) {
        float v = (lane < THREADS / 32) ? sh_part[lane] : 0.0f;
        #pragma unroll
        for (int o = 8; o > 0; o >>= 1)
            v += __shfl_down_sync(0xffffffffu, v, o);
        if (lane == 0) sh_n = v;
    }
    __syncthreads();

    // ---- scatter-accumulate into our own freshly-written (L2-hot) row ----
    // Duplicate tokens sum to count*idf*inv_n automatically; RED = no-return.
    const float inv_n = 1.0f / sh_n;
    atomicAdd(&orow[tok0], idf0 * inv_n);
    atomicAdd(&orow[tok1], idf1 * inv_n);
}

extern "C" void kernel_launch(void* const* d_in, const int* in_sizes, int n_in,
                              void* d_out, int out_size)
{
    const void*  x   = d_in[0];
    const float* idf = (const float*)d_in[1];
    float*       out = (float*)d_out;

    tfidf_kernel<<<BATCH, THREADS>>>(x, idf, out);
}